// round 10
// baseline (speedup 1.0000x reference)
#include <cuda_runtime.h>

typedef unsigned long long u64;

#define SEQ   20
#define FEAT  5
#define NU1   10
#define NU2   7
#define NU3   4
#define NOUT  4
#define NBATCH 262144
#define NT    128
#define NELEM 3
#define EPB   (NT * NELEM)          // 384 elements per block
#define NBLOCKS ((NBATCH + EPB - 1) / EPB)   // 683 (last block partially valid)
#define TCHUNK 5

// ---------------- packed f32x2 helpers ----------------
__device__ __forceinline__ u64 pack2(float lo, float hi) {
    u64 r; asm("mov.b64 %0, {%1, %2};" : "=l"(r) : "f"(lo), "f"(hi)); return r;
}
__device__ __forceinline__ void unpack2(u64 v, float& lo, float& hi) {
    asm("mov.b64 {%0, %1}, %2;" : "=f"(lo), "=f"(hi) : "l"(v));
}
__device__ __forceinline__ u64 ffma2(u64 a, u64 b, u64 c) {
    u64 d; asm("fma.rn.f32x2 %0, %1, %2, %3;" : "=l"(d) : "l"(a), "l"(b), "l"(c)); return d;
}
__device__ __forceinline__ u64 fmul2(u64 a, u64 b) {
    u64 d; asm("mul.rn.f32x2 %0, %1, %2;" : "=l"(d) : "l"(a), "l"(b)); return d;
}
__device__ __forceinline__ float hadd2(u64 v) {
    float a, b; unpack2(v, a, b); return a + b;
}

// ---------------- single-MUFU nonlinearities ----------------
__device__ __forceinline__ float tanh1(float x) {
    float y; asm("tanh.approx.f32 %0, %1;" : "=f"(y) : "f"(x)); return y;
}
// sigmoid(x) = 0.5*tanh(x/2)+0.5 ; the /2 pre-folded into i/f/o weights+biases.
__device__ __forceinline__ float sigf(float zhalf) {
    return fmaf(0.5f, tanh1(zhalf), 0.5f);
}

// ---------------- k-packed layer geometry ----------------
// Layer k-row sequences (bias carried by a constant-1.0 input slot):
//  L1: [x0..x4, 1.0 (bias row), h1(10)]            KD=16, KP=8, DP=3 x-pairs, PH=5
//  L2: [h1(10), h2old(8: units0..6 + 1.0 (bias))]  KD=18, KP=9, DP=5,          PH=4
//  L3: [h2(8: incl 1.0 (bias row)), h3old(4)]      KD=12, KP=6, DP=4,          PH=2
// Weight smem layout per layer: float4 at ((kp*PH + p)*4 + g); float4 =
//   {W[2kp][u0], W[2kp+1][u0], W[2kp][u1], W[2kp+1][u1]}  (pre-scaled)

constexpr int OFF_W1 = 0;                 // 8*5*16  = 640
constexpr int OFF_W2 = 640;               // 9*4*16  = 576
constexpr int OFF_W3 = 1216;              // 6*2*16  = 192
constexpr int OFF_WD = 1408;              // [kp][o] u64 -> 16 floats
constexpr int OFF_BD = 1424;              // 4 u64 (0.5*bd, 0) -> 8 floats
constexpr int OFF_XS = 1432;              // x chunk: [EPB rows][30 cols]
constexpr int XSTRIDE = 30;               // 15 u64 -> conflict-free LDS.64
constexpr int OFF_CS = OFF_XS + EPB * XSTRIDE;      // c: 3*22 slots * NT floats
constexpr int NCSL   = 22;                // c slots/elem: L1 10, L2 8, L3 4
constexpr int SMEM_FLOATS = OFF_CS + NELEM * NCSL * NT;
constexpr int SMEM_BYTES  = SMEM_FLOATS * 4;        // ~85.6 KB

constexpr int CS_L1 = 0, CS_L2 = 10, CS_L3 = 18;

// ---------------- weight prep into k-packed smem ----------------
__device__ __forceinline__ void pack_layer(float* dst,
                                           const float* __restrict__ Wk,
                                           const float* __restrict__ Wr,
                                           const float* __restrict__ b,
                                           int wkRows, int biasPos, int wrStart,
                                           int KD, int U, int PH) {
    int total = (KD / 2) * PH * 16;
    for (int i = threadIdx.x; i < total; i += blockDim.x) {
        int f = i & 3;              // within float4
        int g = (i >> 2) & 3;       // gate
        int rem = i >> 4;           // kp*PH + p
        int p = rem % PH, kp = rem / PH;
        int j = f >> 1, kk = f & 1;
        int u = 2 * p + j;
        int k = 2 * kp + kk;
        float v = 0.0f;
        if (u < U) {
            float sc = (g == 2) ? 1.0f : 0.5f;
            if (k == biasPos)      v = sc * b[g * U + u];
            else if (k < wkRows)   v = sc * Wk[k * 4 * U + g * U + u];
            else                   v = sc * Wr[(k - wrStart) * 4 * U + g * U + u];
        }
        dst[i] = v;
    }
}

// ---------------- one k-packed LSTM layer step, 3 elements ----------------
template<int DP, int PH, bool FORCE1>
__device__ __forceinline__ void layer_stepK(const u64 (&din)[NELEM][DP],
                                            u64 (&h)[NELEM][PH],
                                            float* __restrict__ cb,   // cs + tid
                                            int cOff,
                                            const float* __restrict__ w) {
    u64 old[NELEM][PH];
#pragma unroll
    for (int e = 0; e < NELEM; e++)
#pragma unroll
        for (int i = 0; i < PH; i++) old[e][i] = h[e][i];

#pragma unroll 1
    for (int p = 0; p < PH; p++) {
        const float* wp = w + p * 16;
        u64 z[NELEM][8];
        {   // kp = 0 (always an x/din pair): init accumulators with FMUL2
            ulonglong2 g0 = *(const ulonglong2*)(wp);
            ulonglong2 g1 = *(const ulonglong2*)(wp + 4);
            ulonglong2 g2 = *(const ulonglong2*)(wp + 8);
            ulonglong2 g3 = *(const ulonglong2*)(wp + 12);
#pragma unroll
            for (int e = 0; e < NELEM; e++) {
                u64 m = din[e][0];
                z[e][0] = fmul2(m, g0.x); z[e][1] = fmul2(m, g0.y);
                z[e][2] = fmul2(m, g1.x); z[e][3] = fmul2(m, g1.y);
                z[e][4] = fmul2(m, g2.x); z[e][5] = fmul2(m, g2.y);
                z[e][6] = fmul2(m, g3.x); z[e][7] = fmul2(m, g3.y);
            }
        }
#pragma unroll
        for (int kp = 1; kp < DP + PH; kp++) {
            const float* row = wp + kp * PH * 16;
            ulonglong2 g0 = *(const ulonglong2*)(row);
            ulonglong2 g1 = *(const ulonglong2*)(row + 4);
            ulonglong2 g2 = *(const ulonglong2*)(row + 8);
            ulonglong2 g3 = *(const ulonglong2*)(row + 12);
#pragma unroll
            for (int e = 0; e < NELEM; e++) {
                u64 m = (kp < DP) ? din[e][kp] : old[e][kp - DP];
                z[e][0] = ffma2(m, g0.x, z[e][0]); z[e][1] = ffma2(m, g0.y, z[e][1]);
                z[e][2] = ffma2(m, g1.x, z[e][2]); z[e][3] = ffma2(m, g1.y, z[e][3]);
                z[e][4] = ffma2(m, g2.x, z[e][4]); z[e][5] = ffma2(m, g2.y, z[e][5]);
                z[e][6] = ffma2(m, g3.x, z[e][6]); z[e][7] = ffma2(m, g3.y, z[e][7]);
            }
        }
        // pointwise (scalar per unit; bias already accumulated via 1.0 slot)
#pragma unroll
        for (int e = 0; e < NELEM; e++) {
            float i0 = sigf(hadd2(z[e][0])), i1 = sigf(hadd2(z[e][1]));
            float f0 = sigf(hadd2(z[e][2])), f1 = sigf(hadd2(z[e][3]));
            float g0v = tanh1(hadd2(z[e][4])), g1v = tanh1(hadd2(z[e][5]));
            float o0 = sigf(hadd2(z[e][6])), o1 = sigf(hadd2(z[e][7]));
            float* cp = cb + (e * NCSL + cOff + 2 * p) * NT;
            float c0 = cp[0], c1 = cp[NT];
            c0 = fmaf(f0, c0, i0 * g0v);
            c1 = fmaf(f1, c1, i1 * g1v);
            cp[0] = c0; cp[NT] = c1;
            float h0 = o0 * tanh1(c0);
            float h1v = o1 * tanh1(c1);
            if (FORCE1 && p == PH - 1) h1v = 1.0f;   // layer2 pad unit carries bias-1.0
            h[e][p] = pack2(h0, h1v);
        }
    }
}

// ---------------- fused kernel ----------------
__global__ void __launch_bounds__(NT, 2)
lstm3_kernel(const float* __restrict__ x,
             const float* __restrict__ Wk1, const float* __restrict__ Wr1, const float* __restrict__ b1,
             const float* __restrict__ Wk2, const float* __restrict__ Wr2, const float* __restrict__ b2,
             const float* __restrict__ Wk3, const float* __restrict__ Wr3, const float* __restrict__ b3,
             const float* __restrict__ Wd,  const float* __restrict__ bd,
             float* __restrict__ out) {
    extern __shared__ float s[];

    // ---- weight prep (k-packed, pre-scaled, bias folded into 1.0 slots) ----
    pack_layer(s + OFF_W1, Wk1, Wr1, b1,  5,  5,  6, 16, NU1, 5);
    pack_layer(s + OFF_W2, Wk2, Wr2, b2, 10, 17, 10, 18, NU2 + 1, 4);  // U=8: unit7 cols zeroed below
    pack_layer(s + OFF_W3, Wk3, Wr3, b3,  7,  7,  8, 12, NU3, 2);
    // NOTE: pack_layer for L2 was called with U=8 which would index OOB; redo L2 properly:
    // (handled below with explicit U=7 + zero pad)
    __syncthreads();
    // L2 re-pack with correct U=7 (unit 7 => zero weights)
    pack_layer(s + OFF_W2, Wk2, Wr2, b2, 10, 17, 10, 18, NU2, 4);
    // dense: [kp][o] u64 pairs, pre-halved; bias pairs (0.5*bd, 0)
    for (int i = threadIdx.x; i < 8; i += blockDim.x) {
        int kp = i >> 2, o = i & 3;
        s[OFF_WD + i * 2]     = 0.5f * Wd[(2 * kp) * 4 + o];
        s[OFF_WD + i * 2 + 1] = 0.5f * Wd[(2 * kp + 1) * 4 + o];
    }
    for (int o = threadIdx.x; o < 4; o += blockDim.x) {
        s[OFF_BD + o * 2]     = 0.5f * bd[o];
        s[OFF_BD + o * 2 + 1] = 0.0f;
    }
    // zero c-state
    for (int i = threadIdx.x; i < NELEM * NCSL * NT; i += blockDim.x)
        s[OFF_CS + i] = 0.0f;

    const int tid = threadIdx.x;
    const int blockBase = blockIdx.x * EPB;
    float* xs = s + OFF_XS;
    float* cb = s + OFF_CS + tid;

    bool val[NELEM];
    float* op[NELEM];
#pragma unroll
    for (int e = 0; e < NELEM; e++) {
        int gid = blockBase + e * NT + tid;
        val[e] = gid < NBATCH;
        op[e] = out + (size_t)gid * (SEQ * NOUT);
    }

    // h state: pair-packed; layer2 pair 3 hi-lane starts at 1.0 (bias carrier)
    u64 h1[NELEM][5], h2[NELEM][4], h3[NELEM][2];
#pragma unroll
    for (int e = 0; e < NELEM; e++) {
#pragma unroll
        for (int i = 0; i < 5; i++) h1[e][i] = 0ull;
#pragma unroll
        for (int i = 0; i < 4; i++) h2[e][i] = 0ull;
        h2[e][3] = pack2(0.0f, 1.0f);
#pragma unroll
        for (int i = 0; i < 2; i++) h3[e][i] = 0ull;
    }

#pragma unroll 1
    for (int cc = 0; cc < SEQ / TCHUNK; cc++) {
        // stage TCHUNK timesteps of x (+1.0 slot per t): xs[row][30]
        __syncthreads();
        for (int i = tid; i < EPB * XSTRIDE; i += NT) {
            int r = i / XSTRIDE, c = i - r * XSTRIDE;
            int ts = c / 6, j = c - ts * 6;
            int grow = blockBase + r;
            if (grow >= NBATCH) grow = NBATCH - 1;   // clamp (masked at store)
            float v = 1.0f;
            if (j < FEAT)
                v = x[(size_t)grow * (SEQ * FEAT) + (cc * TCHUNK + ts) * FEAT + j];
            xs[i] = v;
        }
        __syncthreads();

#pragma unroll 1
        for (int ts = 0; ts < TCHUNK; ts++) {
            int t = cc * TCHUNK + ts;
            // x k-pairs: (x0,x1),(x2,x3),(x4,1.0) per element
            u64 xp[NELEM][3];
#pragma unroll
            for (int e = 0; e < NELEM; e++) {
                const float* xr = xs + (e * NT + tid) * XSTRIDE + ts * 6;
#pragma unroll
                for (int kp = 0; kp < 3; kp++)
                    xp[e][kp] = *(const u64*)(xr + kp * 2);
            }

            layer_stepK<3, 5, false>(xp, h1, cb, CS_L1, s + OFF_W1);
            layer_stepK<5, 4, true >(h1, h2, cb, CS_L2, s + OFF_W2);
            layer_stepK<4, 2, false>(h2, h3, cb, CS_L3, s + OFF_W3);

            // dense 4x4 + sigmoid (k-packed over h3 pairs, pre-halved weights)
#pragma unroll
            for (int e = 0; e < NELEM; e++) {
                float r[4];
#pragma unroll
                for (int o = 0; o < 4; o++) {
                    u64 z = *(const u64*)(s + OFF_BD + o * 2);
                    z = ffma2(h3[e][0], *(const u64*)(s + OFF_WD + (0 * 4 + o) * 2), z);
                    z = ffma2(h3[e][1], *(const u64*)(s + OFF_WD + (1 * 4 + o) * 2), z);
                    r[o] = fmaf(0.5f, tanh1(hadd2(z)), 0.5f);
                }
                if (val[e])
                    *(float4*)(op[e] + t * NOUT) = make_float4(r[0], r[1], r[2], r[3]);
            }
        }
    }
}

extern "C" void kernel_launch(void* const* d_in, const int* in_sizes, int n_in,
                              void* d_out, int out_size) {
    const float* x   = (const float*)d_in[0];
    const float* Wk1 = (const float*)d_in[1];
    const float* Wr1 = (const float*)d_in[2];
    const float* b1  = (const float*)d_in[3];
    const float* Wk2 = (const float*)d_in[4];
    const float* Wr2 = (const float*)d_in[5];
    const float* b2  = (const float*)d_in[6];
    const float* Wk3 = (const float*)d_in[7];
    const float* Wr3 = (const float*)d_in[8];
    const float* b3  = (const float*)d_in[9];
    const float* Wd  = (const float*)d_in[10];
    const float* bd  = (const float*)d_in[11];

    cudaFuncSetAttribute(lstm3_kernel, cudaFuncAttributeMaxDynamicSharedMemorySize, SMEM_BYTES);

    lstm3_kernel<<<NBLOCKS, NT, SMEM_BYTES>>>(
        x, Wk1, Wr1, b1, Wk2, Wr2, b2, Wk3, Wr3, b3, Wd, bd, (float*)d_out);
}

// round 11
// speedup vs baseline: 1.4051x; 1.4051x over previous
#include <cuda_runtime.h>

typedef unsigned long long u64;

#define SEQ   20
#define FEAT  5
#define NU1   10
#define NU2   7
#define NU3   4
#define NOUT  4
#define NBATCH 262144
#define NT    128
#define NELEM 3
#define EPB   (NT * NELEM)                    // 384
#define NBLOCKS ((NBATCH + EPB - 1) / EPB)    // 683 (last block: 256 valid)
#define TCHUNK 4

// ---------------- packed f32x2 helpers ----------------
__device__ __forceinline__ u64 pack2(float lo, float hi) {
    u64 r; asm("mov.b64 %0, {%1, %2};" : "=l"(r) : "f"(lo), "f"(hi)); return r;
}
__device__ __forceinline__ u64 dup2(float s) {
    u64 r; asm("mov.b64 %0, {%1, %1};" : "=l"(r) : "f"(s)); return r;
}
__device__ __forceinline__ void unpack2(u64 v, float& lo, float& hi) {
    asm("mov.b64 {%0, %1}, %2;" : "=f"(lo), "=f"(hi) : "l"(v));
}
__device__ __forceinline__ u64 ffma2(u64 a, u64 b, u64 c) {
    u64 d; asm("fma.rn.f32x2 %0, %1, %2, %3;" : "=l"(d) : "l"(a), "l"(b), "l"(c)); return d;
}
__device__ __forceinline__ u64 fmul2(u64 a, u64 b) {
    u64 d; asm("mul.rn.f32x2 %0, %1, %2;" : "=l"(d) : "l"(a), "l"(b)); return d;
}

// ---------------- single-MUFU nonlinearities ----------------
__device__ __forceinline__ float tanh1(float x) {
    float y; asm("tanh.approx.f32 %0, %1;" : "=f"(y) : "f"(x)); return y;
}
__device__ __forceinline__ u64 tanh2(u64 v) {
    float a, b; unpack2(v, a, b);
    return pack2(tanh1(a), tanh1(b));
}
// sigmoid(x) = 0.5*tanh(x/2) + 0.5 ; the /2 pre-folded into i/f/o weights.
__device__ __forceinline__ u64 sigh2(u64 zhalf, u64 H2) {
    return ffma2(tanh2(zhalf), H2, H2);
}

// ---------------- shared-memory layout (float offsets, dynamic smem) ----------
constexpr int OFF_W1 = 0;      // 15 rows * 5 PH * 4 g * 2 = 600
constexpr int OFF_B1 = 600;    // 40
constexpr int OFF_W2 = 640;    // 17 * 4 * 4 * 2 = 544 (U2 cols padded 7->8)
constexpr int OFF_B2 = 1184;   // 32
constexpr int OFF_W3 = 1216;   // 11 * 2 * 4 * 2 = 176
constexpr int OFF_B3 = 1392;   // 16
constexpr int OFF_WD = 1408;   // 16
constexpr int OFF_BD = 1424;   // 4
constexpr int OFF_XS = 1428;   // x chunk: [EPB rows][TCHUNK*FEAT cols]
constexpr int XCOLS  = TCHUNK * FEAT;                       // 20
constexpr int OFF_CS = OFF_XS + EPB * XCOLS;                // 9108 (8B-aligned: 9108*4/8 int)
constexpr int NCPAIR = 11;                                  // c pairs/elem: L1 5, L2 4, L3 2
constexpr int SMEM_FLOATS = OFF_CS + NELEM * NCPAIR * NT * 2;  // + 8448 = 17556
constexpr int SMEM_BYTES  = SMEM_FLOATS * 4;                // 70224 B (x3 blocks = 211KB)

constexpr int CP_L1 = 0, CP_L2 = 5, CP_L3 = 9;

// gate scale: i,f,o get 0.5 (sigmoid-via-tanh), g(cell) gets 1.0
__device__ __forceinline__ float gate_scale(int g) { return (g == 2) ? 1.0f : 0.5f; }

__device__ __forceinline__ void load_wcomb(float* dst, const float* __restrict__ Wk,
                                           const float* __restrict__ Wr,
                                           int D, int U, int PH) {
    int total = (D + U) * PH * 4;
    for (int idx = threadIdx.x; idx < total; idx += blockDim.x) {
        int row = idx / (PH * 4);
        int rem = idx - row * (PH * 4);
        int p = rem >> 2, g = rem & 3;
        const float* src = (row < D) ? (Wk + row * 4 * U) : (Wr + (row - D) * 4 * U);
        float sc = gate_scale(g);
        int u0 = 2 * p, u1 = u0 + 1;
        dst[2 * idx]     = (u0 < U) ? sc * src[g * U + u0] : 0.0f;
        dst[2 * idx + 1] = (u1 < U) ? sc * src[g * U + u1] : 0.0f;
    }
}
__device__ __forceinline__ void load_bias(float* dst, const float* __restrict__ b,
                                          int U, int PH) {
    int total = PH * 4;
    for (int idx = threadIdx.x; idx < total; idx += blockDim.x) {
        int p = idx >> 2, g = idx & 3;
        float sc = gate_scale(g);
        int u0 = 2 * p, u1 = u0 + 1;
        dst[2 * idx]     = (u0 < U) ? sc * b[g * U + u0] : 0.0f;
        dst[2 * idx + 1] = (u1 < U) ? sc * b[g * U + u1] : 0.0f;
    }
}

// ---------------- LSTM layer step: 3 elements share every weight load --------
// p-loop NOT unrolled. Gates computed in two halves (i,f then g,o) with the
// sigmoid applied between halves, capping live accumulator state at ~15 u64.
// DN/UN are array extents (>= D/U); D/U are the logical counts.
template<int D, int DN, int U, int UN, int PH>
__device__ __forceinline__ void layer_step3(const float (&din)[NELEM][DN],
                                            float (&h)[NELEM][UN],
                                            u64* __restrict__ cs, int cOff,
                                            const float* __restrict__ w,
                                            const float* __restrict__ bias, u64 H2) {
    float old[NELEM][U];
#pragma unroll
    for (int e = 0; e < NELEM; e++)
#pragma unroll
        for (int i = 0; i < U; i++) old[e][i] = h[e][i];

#pragma unroll 1
    for (int p = 0; p < PH; p++) {
        u64 cOld[NELEM];
#pragma unroll
        for (int e = 0; e < NELEM; e++)
            cOld[e] = cs[(e * NCPAIR + cOff + p) * NT];

        // ---- half 0: gates i, f ----
        u64 zi[NELEM], zf[NELEM];
        {
            ulonglong2 bv = *(const ulonglong2*)(bias + p * 8);
#pragma unroll
            for (int e = 0; e < NELEM; e++) { zi[e] = bv.x; zf[e] = bv.y; }
#pragma unroll
            for (int k = 0; k < D + U; k++) {
                ulonglong2 w0 = *(const ulonglong2*)(w + (k * PH + p) * 8);
#pragma unroll
                for (int e = 0; e < NELEM; e++) {
                    u64 m = dup2((k < D) ? din[e][k] : old[e][k - D]);
                    zi[e] = ffma2(m, w0.x, zi[e]);
                    zf[e] = ffma2(m, w0.y, zf[e]);
                }
            }
        }
        u64 iv[NELEM], fv[NELEM];
#pragma unroll
        for (int e = 0; e < NELEM; e++) {
            iv[e] = sigh2(zi[e], H2);
            fv[e] = sigh2(zf[e], H2);
        }

        // ---- half 1: gates g, o ----
        u64 zg[NELEM], zo[NELEM];
        {
            ulonglong2 bv = *(const ulonglong2*)(bias + p * 8 + 4);
#pragma unroll
            for (int e = 0; e < NELEM; e++) { zg[e] = bv.x; zo[e] = bv.y; }
#pragma unroll
            for (int k = 0; k < D + U; k++) {
                ulonglong2 w1 = *(const ulonglong2*)(w + (k * PH + p) * 8 + 4);
#pragma unroll
                for (int e = 0; e < NELEM; e++) {
                    u64 m = dup2((k < D) ? din[e][k] : old[e][k - D]);
                    zg[e] = ffma2(m, w1.x, zg[e]);
                    zo[e] = ffma2(m, w1.y, zo[e]);
                }
            }
        }
#pragma unroll
        for (int e = 0; e < NELEM; e++) {
            u64 gv = tanh2(zg[e]);
            u64 ov = sigh2(zo[e], H2);
            u64 cn = ffma2(fv[e], cOld[e], fmul2(iv[e], gv));
            cs[(e * NCPAIR + cOff + p) * NT] = cn;
            u64 hn = fmul2(ov, tanh2(cn));
            unpack2(hn, h[e][2 * p], h[e][2 * p + 1]);
        }
    }
}

// ---------------- fused kernel ----------------
__global__ void __launch_bounds__(NT, 3)
lstm3_kernel(const float* __restrict__ x,
             const float* __restrict__ Wk1, const float* __restrict__ Wr1, const float* __restrict__ b1,
             const float* __restrict__ Wk2, const float* __restrict__ Wr2, const float* __restrict__ b2,
             const float* __restrict__ Wk3, const float* __restrict__ Wr3, const float* __restrict__ b3,
             const float* __restrict__ Wd,  const float* __restrict__ bd,
             float* __restrict__ out) {
    extern __shared__ float s[];

    load_wcomb(s + OFF_W1, Wk1, Wr1, FEAT, NU1, 5);
    load_bias (s + OFF_B1, b1, NU1, 5);
    load_wcomb(s + OFF_W2, Wk2, Wr2, NU1, NU2, 4);
    load_bias (s + OFF_B2, b2, NU2, 4);
    load_wcomb(s + OFF_W3, Wk3, Wr3, NU2, NU3, 2);
    load_bias (s + OFF_B3, b3, NU3, 2);
    for (int idx = threadIdx.x; idx < 8; idx += blockDim.x) {
        int k = idx >> 1, p = idx & 1;
        s[OFF_WD + 2 * idx]     = 0.5f * Wd[k * 4 + 2 * p];
        s[OFF_WD + 2 * idx + 1] = 0.5f * Wd[k * 4 + 2 * p + 1];
    }
    for (int idx = threadIdx.x; idx < 4; idx += blockDim.x)
        s[OFF_BD + idx] = 0.5f * bd[idx];

    const int tid = threadIdx.x;
    const u64 H2 = pack2(0.5f, 0.5f);
    const int blockBase = blockIdx.x * EPB;
    float* xs = s + OFF_XS;
    u64* cs = (u64*)(s + OFF_CS) + tid;

    // zero c-state in smem
    {
        u64* cz = (u64*)(s + OFF_CS);
        for (int i = tid; i < NELEM * NCPAIR * NT; i += NT) cz[i] = 0ull;
    }

    bool val[NELEM];
    float* op[NELEM];
#pragma unroll
    for (int e = 0; e < NELEM; e++) {
        int gid = blockBase + e * NT + tid;
        val[e] = gid < NBATCH;
        op[e] = out + (size_t)gid * (SEQ * NOUT);
    }

    // h state: scalars in registers
    float h1[NELEM][NU1], h2[NELEM][8], h3[NELEM][NU3];
#pragma unroll
    for (int e = 0; e < NELEM; e++) {
#pragma unroll
        for (int i = 0; i < NU1; i++) h1[e][i] = 0.0f;
#pragma unroll
        for (int i = 0; i < 8; i++)   h2[e][i] = 0.0f;
#pragma unroll
        for (int i = 0; i < NU3; i++) h3[e][i] = 0.0f;
    }

#pragma unroll 1
    for (int cc = 0; cc < SEQ / TCHUNK; cc++) {
        // stage TCHUNK timesteps of x for all EPB rows (clamped; masked at store)
        __syncthreads();
        for (int i = tid; i < EPB * XCOLS; i += NT) {
            int r = i / XCOLS, col = i - r * XCOLS;
            int grow = blockBase + r;
            if (grow >= NBATCH) grow = NBATCH - 1;
            xs[i] = x[(size_t)grow * (SEQ * FEAT) + cc * XCOLS + col];
        }
        __syncthreads();

#pragma unroll 1
        for (int ts = 0; ts < TCHUNK; ts++) {
            int t = cc * TCHUNK + ts;
            float xv[NELEM][FEAT];
#pragma unroll
            for (int e = 0; e < NELEM; e++)
#pragma unroll
                for (int k = 0; k < FEAT; k++)
                    xv[e][k] = xs[(e * NT + tid) * XCOLS + ts * FEAT + k];

            layer_step3<FEAT, FEAT, NU1, NU1, 5>(xv, h1, cs, CP_L1, s + OFF_W1, s + OFF_B1, H2);
            layer_step3<NU1,  NU1,  NU2, 8,   4>(h1, h2, cs, CP_L2, s + OFF_W2, s + OFF_B2, H2);
            layer_step3<NU2,  8,    NU3, NU3, 2>(h2, h3, cs, CP_L3, s + OFF_W3, s + OFF_B3, H2);

            // dense 4x4 + sigmoid (weights pre-halved)
            ulonglong2 bdv = *(const ulonglong2*)(s + OFF_BD);
#pragma unroll
            for (int e = 0; e < NELEM; e++) {
                u64 z0 = bdv.x, z1 = bdv.y;
#pragma unroll
                for (int k = 0; k < NU3; k++) {
                    u64 m = dup2(h3[e][k]);
                    ulonglong2 w = *(const ulonglong2*)(s + OFF_WD + k * 4);
                    z0 = ffma2(m, w.x, z0);
                    z1 = ffma2(m, w.y, z1);
                }
                u64 r0 = sigh2(z0, H2), r1 = sigh2(z1, H2);
                float o0, o1, o2, o3;
                unpack2(r0, o0, o1);
                unpack2(r1, o2, o3);
                if (val[e])
                    *(float4*)(op[e] + t * NOUT) = make_float4(o0, o1, o2, o3);
            }
        }
    }
}

extern "C" void kernel_launch(void* const* d_in, const int* in_sizes, int n_in,
                              void* d_out, int out_size) {
    const float* x   = (const float*)d_in[0];
    const float* Wk1 = (const float*)d_in[1];
    const float* Wr1 = (const float*)d_in[2];
    const float* b1  = (const float*)d_in[3];
    const float* Wk2 = (const float*)d_in[4];
    const float* Wr2 = (const float*)d_in[5];
    const float* b2  = (const float*)d_in[6];
    const float* Wk3 = (const float*)d_in[7];
    const float* Wr3 = (const float*)d_in[8];
    const float* b3  = (const float*)d_in[9];
    const float* Wd  = (const float*)d_in[10];
    const float* bd  = (const float*)d_in[11];

    cudaFuncSetAttribute(lstm3_kernel, cudaFuncAttributeMaxDynamicSharedMemorySize, SMEM_BYTES);

    lstm3_kernel<<<NBLOCKS, NT, SMEM_BYTES>>>(
        x, Wk1, Wr1, b1, Wk2, Wr2, b2, Wk3, Wr3, b3, Wd, bd, (float*)d_out);
}